// round 9
// baseline (speedup 1.0000x reference)
#include <cuda_runtime.h>

#define D        128
#define MAX_N    50000
#define TILE_M   64          // node rows per MLP block
#define KHALF    64          // k-rows of W staged per smem pass
#define HSTRIDE  68          // padded stride (floats) of transposed H tile
#define MLP_THREADS 256

// Scratch for aggregated messages (static __device__ globals: allowed, no cudaMalloc)
__device__ float g_mi[MAX_N * D];
__device__ float g_mo[MAX_N * D];
__device__ int   g_idx_is64;   // 1 -> edge_index buffer is int64, 0 -> int32

// ---------------------------------------------------------------------------
// Packed f32x2 helpers (Blackwell sm_100a)
// ---------------------------------------------------------------------------
__device__ __forceinline__ unsigned long long fma2(unsigned long long a,
                                                   unsigned long long b,
                                                   unsigned long long c) {
    unsigned long long d;
    asm("fma.rn.f32x2 %0, %1, %2, %3;" : "=l"(d) : "l"(a), "l"(b), "l"(c));
    return d;
}
__device__ __forceinline__ unsigned long long pack2(float lo, float hi) {
    unsigned long long d;
    asm("mov.b64 %0, {%1, %2};" : "=l"(d) : "f"(lo), "f"(hi));
    return d;
}
__device__ __forceinline__ float2 unpack2(unsigned long long v) {
    float2 r;
    asm("mov.b64 {%0, %1}, %2;" : "=f"(r.x), "=f"(r.y) : "l"(v));
    return r;
}

// ---------------------------------------------------------------------------
// Kernel 0: detect edge_index dtype (int64 vs int32-narrowed by harness).
// ---------------------------------------------------------------------------
__global__ void detect_idx_kernel(const void* __restrict__ eidx, int E, int N) {
    if (threadIdx.x != 0 || blockIdx.x != 0) return;
    const long long* p64 = (const long long*)eidx;
    int stride = E / 64; if (stride < 1) stride = 1;
    int ok = 1;
    for (int i = 0; i < 64; ++i) {
        long long v = p64[(long long)i * stride];
        if (v < 0 || v >= N) { ok = 0; break; }
    }
    g_idx_is64 = ok;
}

// ---------------------------------------------------------------------------
// Kernel 1: zero the message buffers (float4 stores)
// ---------------------------------------------------------------------------
__global__ void zero_kernel(int n4) {
    int i = blockIdx.x * blockDim.x + threadIdx.x;
    if (i < n4) {
        float4 z = make_float4(0.f, 0.f, 0.f, 0.f);
        reinterpret_cast<float4*>(g_mi)[i] = z;
        reinterpret_cast<float4*>(g_mo)[i] = z;
    }
}

// ---------------------------------------------------------------------------
// Kernel 2: edge scatter. One warp per edge; lane l owns floats [4l,4l+4).
// ---------------------------------------------------------------------------
__device__ __forceinline__ void red_add_v4(float* p, float a, float b, float c, float d) {
    asm volatile("red.global.add.v4.f32 [%0], {%1, %2, %3, %4};"
                 :: "l"(p), "f"(a), "f"(b), "f"(c), "f"(d) : "memory");
}

__global__ void scatter_kernel(const float* __restrict__ x,
                               const float* __restrict__ ew,
                               const void* __restrict__ eidx,
                               int E, int N) {
    int gtid = blockIdx.x * blockDim.x + threadIdx.x;
    int edge = gtid >> 5;
    int lane = threadIdx.x & 31;
    if (edge >= E) return;

    int src, dst;
    if (g_idx_is64) {
        const long long* p = (const long long*)eidx;
        src = (int)p[edge];
        dst = (int)p[(size_t)E + edge];
    } else {
        const int* p = (const int*)eidx;
        src = p[edge];
        dst = p[(size_t)E + edge];
    }
    src = min(max(src, 0), N - 1);
    dst = min(max(dst, 0), N - 1);

    float w = ew[edge];

    const float4 vs = reinterpret_cast<const float4*>(x + (size_t)src * D)[lane];
    const float4 vd = reinterpret_cast<const float4*>(x + (size_t)dst * D)[lane];

    float* pi = g_mi + (size_t)dst * D + lane * 4;
    float* po = g_mo + (size_t)src * D + lane * 4;

    red_add_v4(pi, w * vs.x, w * vs.y, w * vs.z, w * vs.w);
    red_add_v4(po, w * vd.x, w * vd.y, w * vd.z, w * vd.w);
}

// ---------------------------------------------------------------------------
// Kernel 3: fused 4-layer MLP — transposed activations, row-packed f32x2.
//   sW: 64x128 k-half of W (32 KB). sHT: transposed H tile, sHT[k][m],
//   stride HSTRIDE=68 floats (16B-aligned rows, bank spread). 66 KB/CTA ->
//   3 CTAs/SM.
//   Thread (cx=tid&31, ry=tid>>5) owns rows [8ry,8ry+8) x cols [4cx,4cx+4).
//   Hot loop per k: 1 LDS.128 (w, contiguous) + 2 LDS.128 (a, broadcast,
//   pre-packed row pairs) + 4 splat movs + 16 fma.rn.f32x2 = ~23 issues.
// ---------------------------------------------------------------------------
__global__ __launch_bounds__(MLP_THREADS, 3)
void mlp_kernel(const float* __restrict__ x,
                const float* __restrict__ W1, const float* __restrict__ b1,
                const float* __restrict__ W2, const float* __restrict__ b2,
                const float* __restrict__ W3, const float* __restrict__ b3,
                const float* __restrict__ W4, const float* __restrict__ b4,
                float* __restrict__ out, int N) {
    extern __shared__ float smem[];
    float* sW  = smem;                 // KHALF*D floats = 32 KB
    float* sHT = smem + KHALF * D;     // D*HSTRIDE floats = 34 KB (transposed)

    const int tid = threadIdx.x;
    const int cx  = tid & 31;    // cols [4*cx, 4*cx+4)
    const int ry  = tid >> 5;    // rows [8*ry, 8*ry+8)
    const int r0  = blockIdx.x * TILE_M;

    unsigned long long acc[4][4];    // [row-pair rp][col j]: rows (8ry+2rp, +1)

    // --- cooperative loaders ---------------------------------------------
    auto loadW = [&](const float* __restrict__ W) {   // one 64x128 k-half
        const float4* w4 = reinterpret_cast<const float4*>(W);
        float4* s4 = reinterpret_cast<float4*>(sW);
        #pragma unroll
        for (int i = 0; i < (KHALF * D / 4) / MLP_THREADS; ++i)
            s4[tid + i * MLP_THREADS] = w4[tid + i * MLP_THREADS];
    };
    // Global (row-major) -> sHT (transposed). Cold path; conflicts OK.
    auto loadHT = [&](const float* __restrict__ src) {
        #pragma unroll
        for (int i = 0; i < (TILE_M * D / 4) / MLP_THREADS; ++i) {
            int idx = tid + i * MLP_THREADS;
            int m   = idx >> 5;            // node row 0..63
            int c4  = (idx & 31) * 4;      // feature 0..124 step 4
            int gr  = r0 + m;
            float4 v = make_float4(0.f, 0.f, 0.f, 0.f);
            if (gr < N)
                v = *reinterpret_cast<const float4*>(src + (size_t)gr * D + c4);
            sHT[(c4 + 0) * HSTRIDE + m] = v.x;
            sHT[(c4 + 1) * HSTRIDE + m] = v.y;
            sHT[(c4 + 2) * HSTRIDE + m] = v.z;
            sHT[(c4 + 3) * HSTRIDE + m] = v.w;
        }
    };
    auto initBias = [&](const float* __restrict__ b) {
        float4 bv = *reinterpret_cast<const float4*>(b + 4 * cx);
        unsigned long long bs[4] = { pack2(bv.x, bv.x), pack2(bv.y, bv.y),
                                     pack2(bv.z, bv.z), pack2(bv.w, bv.w) };
        #pragma unroll
        for (int rp = 0; rp < 4; ++rp)
            #pragma unroll
            for (int j = 0; j < 4; ++j) acc[rp][j] = bs[j];
    };

    // --- packed 64x128x64 GEMM accumulate over one k-half ------------------
    auto gemm_half = [&](int koff) {
        #pragma unroll 4
        for (int k = 0; k < KHALF; ++k) {
            // weights: contiguous 512B across warp, conflict-free
            ulonglong2 wp = *reinterpret_cast<const ulonglong2*>(sW + k * D + 4 * cx);
            float2 w01 = unpack2(wp.x);
            float2 w23 = unpack2(wp.y);
            unsigned long long ws[4] = { pack2(w01.x, w01.x), pack2(w01.y, w01.y),
                                         pack2(w23.x, w23.x), pack2(w23.y, w23.y) };
            // activations: broadcast LDS.128, rows pre-packed in pairs
            const float* ap = sHT + (koff + k) * HSTRIDE + 8 * ry;
            ulonglong2 a01 = *reinterpret_cast<const ulonglong2*>(ap);
            ulonglong2 a23 = *reinterpret_cast<const ulonglong2*>(ap + 4);
            unsigned long long av[4] = { a01.x, a01.y, a23.x, a23.y };
            #pragma unroll
            for (int rp = 0; rp < 4; ++rp)
                #pragma unroll
                for (int j = 0; j < 4; ++j)
                    acc[rp][j] = fma2(av[rp], ws[j], acc[rp][j]);
        }
    };

    auto epilogue_smem = [&]() {
        #pragma unroll
        for (int rp = 0; rp < 4; ++rp)
            #pragma unroll
            for (int j = 0; j < 4; ++j) {
                float2 s = unpack2(acc[rp][j]);
                s.x = tanhf(s.x); s.y = tanhf(s.y);
                // 8B-aligned STS.64 into transposed tile
                *reinterpret_cast<float2*>(sHT + (4 * cx + j) * HSTRIDE
                                           + 8 * ry + 2 * rp) = s;
            }
    };

    // ====================== Layer 1: [mi, mo, x] @ W1 =====================
    initBias(b1);
    #pragma unroll 1
    for (int p = 0; p < 3; ++p) {
        const float* src = (p == 0) ? (const float*)g_mi
                         : (p == 1) ? (const float*)g_mo : x;
        const float* Wp  = W1 + (size_t)p * D * D;
        __syncthreads();                       // prior sHT/sW reads complete
        loadHT(src);
        loadW(Wp);                             // k-half 0
        __syncthreads();
        gemm_half(0);
        __syncthreads();                       // sW half-0 reads complete
        loadW(Wp + (size_t)KHALF * D);         // k-half 1
        __syncthreads();
        gemm_half(KHALF);
    }
    __syncthreads();                           // all sHT reads done
    epilogue_smem();

    // ====================== Layers 2..4 ===================================
    const float* Ws[3] = { W2, W3, W4 };
    const float* bs[3] = { b2, b3, b4 };
    #pragma unroll 1
    for (int l = 0; l < 3; ++l) {
        __syncthreads();                       // sHT writes visible, prev sW reads done
        loadW(Ws[l]);                          // k-half 0
        __syncthreads();
        initBias(bs[l]);
        gemm_half(0);
        __syncthreads();                       // sW half-0 reads complete
        loadW(Ws[l] + (size_t)KHALF * D);      // k-half 1
        __syncthreads();
        gemm_half(KHALF);
        __syncthreads();                       // all sHT/sW reads done
        if (l < 2) {
            epilogue_smem();
        } else {
            #pragma unroll
            for (int rp = 0; rp < 4; ++rp) {
                int gr = r0 + 8 * ry + 2 * rp;
                #pragma unroll
                for (int j = 0; j < 4; ++j) {
                    float2 s = unpack2(acc[rp][j]);
                    if (gr < N)     out[(size_t)gr * D + 4 * cx + j]       = tanhf(s.x);
                    if (gr + 1 < N) out[(size_t)(gr + 1) * D + 4 * cx + j] = tanhf(s.y);
                }
            }
        }
    }
}

// ---------------------------------------------------------------------------
// Host launcher (graph-capturable: kernel launches only)
// ---------------------------------------------------------------------------
extern "C" void kernel_launch(void* const* d_in, const int* in_sizes, int n_in,
                              void* d_out, int out_size) {
    const float* x    = (const float*)d_in[0];
    const float* ew   = (const float*)d_in[1];
    const void*  eidx = d_in[2];
    const float* W1   = (const float*)d_in[3];
    const float* b1   = (const float*)d_in[4];
    const float* W2   = (const float*)d_in[5];
    const float* b2   = (const float*)d_in[6];
    const float* W3   = (const float*)d_in[7];
    const float* b3   = (const float*)d_in[8];
    const float* W4   = (const float*)d_in[9];
    const float* b4   = (const float*)d_in[10];
    float*       out  = (float*)d_out;

    const int N = in_sizes[0] / D;        // 50000
    const int E = in_sizes[2] / 2;        // 800000

    // 0) detect index dtype
    detect_idx_kernel<<<1, 32>>>(eidx, E, N);

    // 1) zero message buffers
    {
        int n4 = N * D / 4;
        zero_kernel<<<(n4 + 255) / 256, 256>>>(n4);
    }

    // 2) edge scatter: one warp per edge
    {
        long long total = (long long)E * 32;
        int blocks = (int)((total + 255) / 256);
        scatter_kernel<<<blocks, 256>>>(x, ew, eidx, E, N);
    }

    // 3) fused MLP
    {
        const int smem = (KHALF * D + D * HSTRIDE) * (int)sizeof(float);  // 67584 B
        cudaFuncSetAttribute(mlp_kernel,
                             cudaFuncAttributeMaxDynamicSharedMemorySize, smem);
        int blocks = (N + TILE_M - 1) / TILE_M;                           // 782
        mlp_kernel<<<blocks, MLP_THREADS, smem>>>(x, W1, b1, W2, b2,
                                                  W3, b3, W4, b4, out, N);
    }
}

// round 11
// speedup vs baseline: 1.4983x; 1.4983x over previous
#include <cuda_runtime.h>
#include <cuda_bf16.h>
#include <cstdint>

#define D        128
#define MAX_N    50000
#define TILE_M   128
#define THREADS  256
#define ASTRIDE  136          // padded bf16 stride: rows 4 banks apart

// Scratch for aggregated messages
__device__ float g_mi[MAX_N * D];
__device__ float g_mo[MAX_N * D];
__device__ int   g_idx_is64;

// Pre-split, pre-transposed weights: 6 chunks of [n=128][k=128] bf16.
// chunks 0-2: W1 k-rows [0,128),[128,256),[256,384); chunks 3-5: W2,W3,W4.
__device__ uint4 g_wt_hi[6 * 128 * 128 / 8];
__device__ uint4 g_wt_lo[6 * 128 * 128 / 8];

// ---------------------------------------------------------------------------
__device__ __forceinline__ void split_bf16(float f, uint16_t& h, uint16_t& l) {
    __nv_bfloat16 hi = __float2bfloat16_rn(f);
    __nv_bfloat16 lo = __float2bfloat16_rn(f - __bfloat162float(hi));
    h = __bfloat16_as_ushort(hi);
    l = __bfloat16_as_ushort(lo);
}

__device__ __forceinline__ void mma16816(float c[4], const uint32_t a[4],
                                         const uint32_t b[2]) {
    asm volatile(
        "mma.sync.aligned.m16n8k16.row.col.f32.bf16.bf16.f32 "
        "{%0,%1,%2,%3}, {%4,%5,%6,%7}, {%8,%9}, {%0,%1,%2,%3};"
        : "+f"(c[0]), "+f"(c[1]), "+f"(c[2]), "+f"(c[3])
        : "r"(a[0]), "r"(a[1]), "r"(a[2]), "r"(a[3]), "r"(b[0]), "r"(b[1]));
}

// ===========================================================================
// Kernel 0/1/2: dtype detect, zero, edge scatter (proven, unchanged)
// ===========================================================================
__global__ void detect_idx_kernel(const void* __restrict__ eidx, int E, int N) {
    if (threadIdx.x != 0 || blockIdx.x != 0) return;
    const long long* p64 = (const long long*)eidx;
    int stride = E / 64; if (stride < 1) stride = 1;
    int ok = 1;
    for (int i = 0; i < 64; ++i) {
        long long v = p64[(long long)i * stride];
        if (v < 0 || v >= N) { ok = 0; break; }
    }
    g_idx_is64 = ok;
}

__global__ void zero_kernel(int n4) {
    int i = blockIdx.x * blockDim.x + threadIdx.x;
    if (i < n4) {
        float4 z = make_float4(0.f, 0.f, 0.f, 0.f);
        reinterpret_cast<float4*>(g_mi)[i] = z;
        reinterpret_cast<float4*>(g_mo)[i] = z;
    }
}

__device__ __forceinline__ void red_add_v4(float* p, float a, float b, float c, float d) {
    asm volatile("red.global.add.v4.f32 [%0], {%1, %2, %3, %4};"
                 :: "l"(p), "f"(a), "f"(b), "f"(c), "f"(d) : "memory");
}

__global__ void scatter_kernel(const float* __restrict__ x,
                               const float* __restrict__ ew,
                               const void* __restrict__ eidx,
                               int E, int N) {
    int gtid = blockIdx.x * blockDim.x + threadIdx.x;
    int edge = gtid >> 5;
    int lane = threadIdx.x & 31;
    if (edge >= E) return;

    int src, dst;
    if (g_idx_is64) {
        const long long* p = (const long long*)eidx;
        src = (int)p[edge];
        dst = (int)p[(size_t)E + edge];
    } else {
        const int* p = (const int*)eidx;
        src = p[edge];
        dst = p[(size_t)E + edge];
    }
    src = min(max(src, 0), N - 1);
    dst = min(max(dst, 0), N - 1);

    float w = ew[edge];
    const float4 vs = reinterpret_cast<const float4*>(x + (size_t)src * D)[lane];
    const float4 vd = reinterpret_cast<const float4*>(x + (size_t)dst * D)[lane];
    float* pi = g_mi + (size_t)dst * D + lane * 4;
    float* po = g_mo + (size_t)src * D + lane * 4;
    red_add_v4(pi, w * vs.x, w * vs.y, w * vs.z, w * vs.w);
    red_add_v4(po, w * vd.x, w * vd.y, w * vd.z, w * vd.w);
}

// ===========================================================================
// Kernel P: pre-split + transpose weights into g_wt_hi/lo [chunk][n][k]
// ===========================================================================
__global__ void prep_w_kernel(const float* __restrict__ W1,
                              const float* __restrict__ W2,
                              const float* __restrict__ W3,
                              const float* __restrict__ W4) {
    int id = blockIdx.x * blockDim.x + threadIdx.x;   // 6*128*128 total
    if (id >= 6 * 128 * 128) return;
    int c = id >> 14;
    int n = (id >> 7) & 127;
    int k = id & 127;
    const float* src = (c < 3) ? (W1 + (size_t)c * 128 * 128)
                     : (c == 3) ? W2 : (c == 4) ? W3 : W4;
    float w = src[(size_t)k * 128 + n];               // W[k][n] -> B[n][k]
    uint16_t h, l;
    split_bf16(w, h, l);
    reinterpret_cast<uint16_t*>(g_wt_hi)[id] = h;
    reinterpret_cast<uint16_t*>(g_wt_lo)[id] = l;
}

// ===========================================================================
// Kernel 3: fused 4-layer MLP, mma.sync m16n8k16 bf16-split (3 products).
//   smem: sA_hi/sA_lo [128][136] bf16, sB_hi/sB_lo [128][136] bf16 = 136 KB.
//   Warp w: rows 32*(w&3).., cols 64*(w>>2)..; frags loaded as scalar LDS.32
//   (conflict-free by the 136-stride padding). Accumulators persist across
//   layer-1's 3 K-chunks in registers.
// ===========================================================================
#define OFF_A_HI  0
#define OFF_A_LO  (OFF_A_HI + 128 * ASTRIDE * 2)
#define OFF_B_HI  (OFF_A_LO + 128 * ASTRIDE * 2)
#define OFF_B_LO  (OFF_B_HI + 128 * ASTRIDE * 2)
#define SMEM_TOTAL (OFF_B_LO + 128 * ASTRIDE * 2)    // 139264 B

__global__ void __launch_bounds__(THREADS, 1)
mlp_mma_kernel(const float* __restrict__ x,
               const float* __restrict__ b1, const float* __restrict__ b2,
               const float* __restrict__ b3, const float* __restrict__ b4,
               float* __restrict__ out, int N) {
    extern __shared__ char smem[];
    uint16_t* sAh = reinterpret_cast<uint16_t*>(smem + OFF_A_HI);
    uint16_t* sAl = reinterpret_cast<uint16_t*>(smem + OFF_A_LO);
    uint16_t* sBh = reinterpret_cast<uint16_t*>(smem + OFF_B_HI);
    uint16_t* sBl = reinterpret_cast<uint16_t*>(smem + OFF_B_LO);

    const int tid  = threadIdx.x;
    const int wid  = tid >> 5;
    const int lane = tid & 31;
    const int gid  = lane >> 2;     // group id 0..7
    const int t4   = lane & 3;      // thread-in-group 0..3
    const int wr0  = (wid & 3) * 32;
    const int wn0  = (wid >> 2) * 64;
    const int r0   = blockIdx.x * TILE_M;

    float c[2][8][4];               // [m-tile][n-tile][frag]

    // ---- A conversion: fp32 row-major -> split bf16 tiles ------------------
    auto loadA = [&](const float* __restrict__ src) {
        #pragma unroll
        for (int i = 0; i < 16; ++i) {
            int idx = tid + i * THREADS;         // float4 id
            int m   = idx >> 5;
            int k4  = (idx & 31) * 4;
            int gr  = r0 + m;
            float4 v = make_float4(0.f, 0.f, 0.f, 0.f);
            if (gr < N)
                v = __ldg(reinterpret_cast<const float4*>(src + (size_t)gr * D + k4));
            uint16_t h0,h1,h2,h3, l0,l1,l2,l3;
            split_bf16(v.x, h0, l0); split_bf16(v.y, h1, l1);
            split_bf16(v.z, h2, l2); split_bf16(v.w, h3, l3);
            int o = m * ASTRIDE + k4;
            *reinterpret_cast<uint2*>(sAh + o) =
                make_uint2((uint32_t)h0 | ((uint32_t)h1 << 16),
                           (uint32_t)h2 | ((uint32_t)h3 << 16));
            *reinterpret_cast<uint2*>(sAl + o) =
                make_uint2((uint32_t)l0 | ((uint32_t)l1 << 16),
                           (uint32_t)l2 | ((uint32_t)l3 << 16));
        }
    };
    // ---- B copy from pre-split global [n][k] -------------------------------
    auto loadB = [&](int chunk) {
        const uint4* gh = g_wt_hi + chunk * (128 * 128 / 8);
        const uint4* gl = g_wt_lo + chunk * (128 * 128 / 8);
        #pragma unroll
        for (int i = 0; i < 8; ++i) {
            int idx = tid + i * THREADS;         // uint4 = 8 bf16
            int n   = idx >> 4;
            int k8  = (idx & 15) * 8;
            int o   = n * ASTRIDE + k8;
            *reinterpret_cast<uint4*>(sBh + o) = __ldg(gh + idx);
            *reinterpret_cast<uint4*>(sBl + o) = __ldg(gl + idx);
        }
    };
    auto initBias = [&](const float* __restrict__ b) {
        #pragma unroll
        for (int nt = 0; nt < 8; ++nt) {
            float2 bv = __ldg(reinterpret_cast<const float2*>(b + wn0 + nt * 8 + 2 * t4));
            #pragma unroll
            for (int mt = 0; mt < 2; ++mt) {
                c[mt][nt][0] = bv.x; c[mt][nt][1] = bv.y;
                c[mt][nt][2] = bv.x; c[mt][nt][3] = bv.y;
            }
        }
    };

    // ---- one 128x128x128 GEMM accumulate (3 split products) ----------------
    auto gemm = [&]() {
        #pragma unroll 1
        for (int ks = 0; ks < 8; ++ks) {
            int k0 = ks * 16;
            uint32_t aH[2][4], aL[2][4], bH[8][2], bL[8][2];
            #pragma unroll
            for (int mt = 0; mt < 2; ++mt) {
                int row = wr0 + mt * 16 + gid;
                int o0 = row * ASTRIDE + k0 + 2 * t4;
                int o1 = (row + 8) * ASTRIDE + k0 + 2 * t4;
                aH[mt][0] = *reinterpret_cast<const uint32_t*>(sAh + o0);
                aH[mt][1] = *reinterpret_cast<const uint32_t*>(sAh + o1);
                aH[mt][2] = *reinterpret_cast<const uint32_t*>(sAh + o0 + 8);
                aH[mt][3] = *reinterpret_cast<const uint32_t*>(sAh + o1 + 8);
                aL[mt][0] = *reinterpret_cast<const uint32_t*>(sAl + o0);
                aL[mt][1] = *reinterpret_cast<const uint32_t*>(sAl + o1);
                aL[mt][2] = *reinterpret_cast<const uint32_t*>(sAl + o0 + 8);
                aL[mt][3] = *reinterpret_cast<const uint32_t*>(sAl + o1 + 8);
            }
            #pragma unroll
            for (int nt = 0; nt < 8; ++nt) {
                int n = wn0 + nt * 8 + gid;
                int o = n * ASTRIDE + k0 + 2 * t4;
                bH[nt][0] = *reinterpret_cast<const uint32_t*>(sBh + o);
                bH[nt][1] = *reinterpret_cast<const uint32_t*>(sBh + o + 8);
                bL[nt][0] = *reinterpret_cast<const uint32_t*>(sBl + o);
                bL[nt][1] = *reinterpret_cast<const uint32_t*>(sBl + o + 8);
            }
            #pragma unroll
            for (int mt = 0; mt < 2; ++mt)
                #pragma unroll
                for (int nt = 0; nt < 8; ++nt) {
                    mma16816(c[mt][nt], aH[mt], bH[nt]);   // hi*hi
                    mma16816(c[mt][nt], aH[mt], bL[nt]);   // hi*lo
                    mma16816(c[mt][nt], aL[mt], bH[nt]);   // lo*hi
                }
        }
    };

    // ---- epilogue: tanh + re-split into sA ---------------------------------
    auto epi_to_A = [&]() {
        #pragma unroll
        for (int mt = 0; mt < 2; ++mt)
            #pragma unroll
            for (int nt = 0; nt < 8; ++nt) {
                int col = wn0 + nt * 8 + 2 * t4;
                #pragma unroll
                for (int half = 0; half < 2; ++half) {
                    int row = wr0 + mt * 16 + gid + half * 8;
                    float t0 = tanhf(c[mt][nt][half * 2 + 0]);
                    float t1 = tanhf(c[mt][nt][half * 2 + 1]);
                    uint16_t h0, l0, h1, l1;
                    split_bf16(t0, h0, l0); split_bf16(t1, h1, l1);
                    int o = row * ASTRIDE + col;
                    *reinterpret_cast<uint32_t*>(sAh + o) = (uint32_t)h0 | ((uint32_t)h1 << 16);
                    *reinterpret_cast<uint32_t*>(sAl + o) = (uint32_t)l0 | ((uint32_t)l1 << 16);
                }
            }
    };

    // ====================== Layer 1: [mi, mo, x] @ W1 ======================
    initBias(b1);
    #pragma unroll 1
    for (int p = 0; p < 3; ++p) {
        __syncthreads();                      // prior smem reads complete
        loadA(p == 0 ? (const float*)g_mi : p == 1 ? (const float*)g_mo : x);
        loadB(p);
        __syncthreads();
        gemm();
    }
    __syncthreads();                          // all warps done reading sA
    epi_to_A();

    // ====================== Layers 2..4 ====================================
    const float* bs[3] = { b2, b3, b4 };
    #pragma unroll 1
    for (int l = 0; l < 3; ++l) {
        __syncthreads();                      // epi writes visible, sB reads done
        loadB(3 + l);
        __syncthreads();
        initBias(bs[l]);
        gemm();
        __syncthreads();                      // all warps done reading sA/sB
        if (l < 2) {
            epi_to_A();
        } else {
            // final: tanh -> fp32 staging over sB region, then coalesced out
            float* sOut = reinterpret_cast<float*>(smem + OFF_B_HI);  // [128][132]
            #pragma unroll
            for (int mt = 0; mt < 2; ++mt)
                #pragma unroll
                for (int nt = 0; nt < 8; ++nt) {
                    int col = wn0 + nt * 8 + 2 * t4;
                    #pragma unroll
                    for (int half = 0; half < 2; ++half) {
                        int row = wr0 + mt * 16 + gid + half * 8;
                        float2 v;
                        v.x = tanhf(c[mt][nt][half * 2 + 0]);
                        v.y = tanhf(c[mt][nt][half * 2 + 1]);
                        *reinterpret_cast<float2*>(sOut + row * 132 + col) = v;
                    }
                }
            __syncthreads();
            #pragma unroll
            for (int i = 0; i < 16; ++i) {
                int idx = tid + i * THREADS;
                int m   = idx >> 5;
                int c4  = (idx & 31) * 4;
                int gr  = r0 + m;
                if (gr < N)
                    *reinterpret_cast<float4*>(out + (size_t)gr * D + c4) =
                        *reinterpret_cast<const float4*>(sOut + m * 132 + c4);
            }
        }
    }
}

// ---------------------------------------------------------------------------
// Host launcher (graph-capturable: kernel launches only)
// ---------------------------------------------------------------------------
extern "C" void kernel_launch(void* const* d_in, const int* in_sizes, int n_in,
                              void* d_out, int out_size) {
    const float* x    = (const float*)d_in[0];
    const float* ew   = (const float*)d_in[1];
    const void*  eidx = d_in[2];
    const float* W1   = (const float*)d_in[3];
    const float* b1   = (const float*)d_in[4];
    const float* W2   = (const float*)d_in[5];
    const float* b2   = (const float*)d_in[6];
    const float* W3   = (const float*)d_in[7];
    const float* b3   = (const float*)d_in[8];
    const float* W4   = (const float*)d_in[9];
    const float* b4   = (const float*)d_in[10];
    float*       out  = (float*)d_out;

    const int N = in_sizes[0] / D;        // 50000
    const int E = in_sizes[2] / 2;        // 800000

    detect_idx_kernel<<<1, 32>>>(eidx, E, N);

    {
        int n4 = N * D / 4;
        zero_kernel<<<(n4 + 255) / 256, 256>>>(n4);
    }
    {   // pre-split/transpose weights (runs concurrently with zero/scatter deps)
        int total = 6 * 128 * 128;
        prep_w_kernel<<<(total + 255) / 256, 256>>>(W1, W2, W3, W4);
    }
    {
        long long total = (long long)E * 32;
        int blocks = (int)((total + 255) / 256);
        scatter_kernel<<<blocks, 256>>>(x, ew, eidx, E, N);
    }
    {
        cudaFuncSetAttribute(mlp_mma_kernel,
                             cudaFuncAttributeMaxDynamicSharedMemorySize, SMEM_TOTAL);
        int blocks = (N + TILE_M - 1) / TILE_M;     // 391
        mlp_mma_kernel<<<blocks, THREADS, SMEM_TOTAL>>>(x, b1, b2, b3, b4, out, N);
    }
}